// round 17
// baseline (speedup 1.0000x reference)
#include <cuda_runtime.h>
#include <cuda_bf16.h>
#include <math.h>
#include <stdint.h>

// Problem: B=64, T=1024, D=512, H=512
//   xw = x @ W[:512] + b              (65536x512x512 GEMM)
//   h_t = tanh(xw_t + h_{t-1} @ Wh)   scan over T=1024
//
// Phase 1: split-bf16 mma.sync GEMM, R16: register prefetch + DOUBLE-
//   BUFFERED smem stages (one barrier/tile; convert+STS overlaps MMA).
//   xw ~= xh@wh + xl@wh + xh@wl, fp32 accumulate.
// Phase 2: EXACT R7 scan (best known): tagged {f32 val, u32 tag} 8B atoms
//   through L2, relaxed, no fences; 16 groups x 8 CTAs.

__device__ float g_xw[64u * 1024u * 512u];  // 128 MB scratch: [b][t][h]
// [buf][group][producerCTA][feature(64)][row(4)] : {f32 val, u32 tag}
__device__ unsigned long long g_hx[2][16][8][64][4];  // 512 KB

#define FMA2(d, a, b, c) \
    asm("fma.rn.f32x2 %0, %1, %2, %3;" : "=l"(d) : "l"(a), "l"(b), "l"(c))
#define ADDF2(d, a, b) \
    asm("add.rn.f32x2 %0, %1, %2;" : "=l"(d) : "l"(a), "l"(b))
#define PACK2(d, lo, hi) \
    asm("mov.b64 %0, {%1, %2};" : "=l"(d) : "f"(lo), "f"(hi))
#define UNPACK2(lo, hi, v) \
    asm("mov.b64 {%0, %1}, %2;" : "=f"(lo), "=f"(hi) : "l"(v))

static __device__ __forceinline__ uint32_t smem_u32(const void* p) {
    uint32_t a;
    asm("{ .reg .u64 t; cvta.to.shared.u64 t, %1; cvt.u32.u64 %0, t; }"
        : "=r"(a) : "l"(p));
    return a;
}

// ===========================================================================
// Phase 1: split-bf16 mma.sync GEMM (double-buffered pipeline)
// ===========================================================================
#define LDM4(r, addr) \
    asm volatile("ldmatrix.sync.aligned.m8n8.x4.shared.b16 {%0,%1,%2,%3}, [%4];" \
                 : "=r"((r)[0]), "=r"((r)[1]), "=r"((r)[2]), "=r"((r)[3]) \
                 : "r"(addr))
#define LDM2T(r, addr) \
    asm volatile("ldmatrix.sync.aligned.m8n8.x2.trans.shared.b16 {%0,%1}, [%2];" \
                 : "=r"((r)[0]), "=r"((r)[1]) \
                 : "r"(addr))
#define MMA16816(d, a, b) \
    asm volatile( \
        "mma.sync.aligned.m16n8k16.row.col.f32.bf16.bf16.f32 " \
        "{%0,%1,%2,%3}, {%4,%5,%6,%7}, {%8,%9}, {%0,%1,%2,%3};" \
        : "+f"((d)[0]), "+f"((d)[1]), "+f"((d)[2]), "+f"((d)[3]) \
        : "r"((a)[0]), "r"((a)[1]), "r"((a)[2]), "r"((a)[3]), \
          "r"((b)[0]), "r"((b)[1]))

static __device__ __forceinline__ void cvt_split4(float4 v, uint2& hh,
                                                  uint2& ll) {
    __nv_bfloat16 h0 = __float2bfloat16(v.x);
    __nv_bfloat16 h1 = __float2bfloat16(v.y);
    __nv_bfloat16 h2 = __float2bfloat16(v.z);
    __nv_bfloat16 h3 = __float2bfloat16(v.w);
    __nv_bfloat16 l0 = __float2bfloat16(v.x - __bfloat162float(h0));
    __nv_bfloat16 l1 = __float2bfloat16(v.y - __bfloat162float(h1));
    __nv_bfloat16 l2 = __float2bfloat16(v.z - __bfloat162float(h2));
    __nv_bfloat16 l3 = __float2bfloat16(v.w - __bfloat162float(h3));
    hh.x = (uint32_t)__bfloat16_as_ushort(h0) |
           ((uint32_t)__bfloat16_as_ushort(h1) << 16);
    hh.y = (uint32_t)__bfloat16_as_ushort(h2) |
           ((uint32_t)__bfloat16_as_ushort(h3) << 16);
    ll.x = (uint32_t)__bfloat16_as_ushort(l0) |
           ((uint32_t)__bfloat16_as_ushort(l1) << 16);
    ll.y = (uint32_t)__bfloat16_as_ushort(l2) |
           ((uint32_t)__bfloat16_as_ushort(l3) << 16);
}

// smem row strides (in b16 units) chosen conflict-free for ldmatrix
static constexpr int A_STR = 40;    // 32 k + 8 pad
static constexpr int B_STR = 136;   // 128 n + 8 pad

__global__ __launch_bounds__(256, 1) void xw_mma(const float* __restrict__ x,
                                                 const float* __restrict__ W,
                                                 const float* __restrict__ bias) {
    __shared__ __align__(16) uint16_t Ah[2][128 * A_STR];
    __shared__ __align__(16) uint16_t Al[2][128 * A_STR];
    __shared__ __align__(16) uint16_t Bh[2][32 * B_STR];
    __shared__ __align__(16) uint16_t Bl[2][32 * B_STR];

    const int tid = threadIdx.x;
    const int wid = tid >> 5;
    const int lane = tid & 31;
    const int wm = wid >> 2;  // 0..1 -> 64 rows
    const int wn = wid & 3;   // 0..3 -> 32 cols
    const int row0 = (blockIdx.x >> 2) << 7;
    const int n0 = (blockIdx.x & 3) << 7;

    uint32_t sAh[2], sAl[2], sBh[2], sBl[2];
#pragma unroll
    for (int st = 0; st < 2; st++) {
        sAh[st] = smem_u32(&Ah[st][0]);
        sAl[st] = smem_u32(&Al[st][0]);
        sBh[st] = smem_u32(&Bh[st][0]);
        sBl[st] = smem_u32(&Bl[st][0]);
    }

    // ldmatrix lane address offsets
    const int arow = (lane & 7) + ((lane >> 3) & 1) * 8;
    const int acol = (lane >> 4) << 3;
    const uint32_t aoff = (uint32_t)(((wm * 64 + arow) * A_STR + acol) * 2);
    const int l4 = lane & 15;
    const uint32_t boff = (uint32_t)((l4 * B_STR + wn * 32) * 2);

    // per-thread fill coordinates (fixed)
    const int fa_row = tid >> 3;          // with it-offset: (idx>>3)
    const int fa_kq = (tid & 7) << 2;
    (void)fa_row; (void)fa_kq;

    float d[4][4][4];
#pragma unroll
    for (int mt = 0; mt < 4; mt++)
#pragma unroll
        for (int nt = 0; nt < 4; nt++)
#pragma unroll
            for (int i = 0; i < 4; i++) d[mt][nt][i] = 0.0f;

    float4 pa[4], pb[4];

    // ---- preload tile 0 + convert into stage 0 -------------------------
#pragma unroll
    for (int it = 0; it < 4; it++) {
        const int idx = tid + (it << 8);
        pa[it] = *(const float4*)&x[(size_t)(row0 + (idx >> 3)) * 512 +
                                    ((idx & 7) << 2)];
        pb[it] = *(const float4*)&W[(size_t)(idx >> 5) * 512 + n0 +
                                    ((idx & 31) << 2)];
    }
#pragma unroll
    for (int it = 0; it < 4; it++) {
        const int idx = tid + (it << 8);
        uint2 hh, ll;
        cvt_split4(pa[it], hh, ll);
        *(uint2*)&Ah[0][(idx >> 3) * A_STR + ((idx & 7) << 2)] = hh;
        *(uint2*)&Al[0][(idx >> 3) * A_STR + ((idx & 7) << 2)] = ll;
        cvt_split4(pb[it], hh, ll);
        *(uint2*)&Bh[0][(idx >> 5) * B_STR + ((idx & 31) << 2)] = hh;
        *(uint2*)&Bl[0][(idx >> 5) * B_STR + ((idx & 31) << 2)] = ll;
    }
    __syncthreads();

    for (int ti = 0; ti < 16; ti++) {
        const int st = ti & 1;
        const int kt = ti << 5;
        const bool have_next = ti < 15;

        // ---- prefetch NEXT tile's fp32 (latency hidden by MMAs) --------
        if (have_next) {
#pragma unroll
            for (int it = 0; it < 4; it++) {
                const int idx = tid + (it << 8);
                pa[it] = *(const float4*)&x[(size_t)(row0 + (idx >> 3)) * 512 +
                                            kt + 32 + ((idx & 7) << 2)];
                pb[it] = *(const float4*)&W[(size_t)(kt + 32 + (idx >> 5)) * 512 +
                                            n0 + ((idx & 31) << 2)];
            }
        }

        // ---- MMA kk=0 on stage st --------------------------------------
#pragma unroll
        for (int kk = 0; kk < 32; kk += 16) {
            uint32_t ah[4][4], al[4][4], bh[4][2], bl[4][2];
#pragma unroll
            for (int mt = 0; mt < 4; mt++) {
                const uint32_t ao =
                    aoff + (uint32_t)(mt * 16 * A_STR * 2 + kk * 2);
                LDM4(ah[mt], sAh[st] + ao);
                LDM4(al[mt], sAl[st] + ao);
            }
#pragma unroll
            for (int nt = 0; nt < 4; nt++) {
                const uint32_t bo =
                    boff + (uint32_t)(nt * 16 + kk * B_STR * 2);
                LDM2T(bh[nt], sBh[st] + bo);
                LDM2T(bl[nt], sBl[st] + bo);
            }
#pragma unroll
            for (int mt = 0; mt < 4; mt++) {
#pragma unroll
                for (int nt = 0; nt < 4; nt++) {
                    MMA16816(d[mt][nt], ah[mt], bh[nt]);
                    MMA16816(d[mt][nt], al[mt], bh[nt]);
                    MMA16816(d[mt][nt], ah[mt], bl[nt]);
                }
            }
            // after the first k16 group, push next tile into other stage
            if (kk == 0 && have_next) {
                const int so = st ^ 1;
#pragma unroll
                for (int it = 0; it < 4; it++) {
                    const int idx = tid + (it << 8);
                    uint2 hh, ll;
                    cvt_split4(pa[it], hh, ll);
                    *(uint2*)&Ah[so][(idx >> 3) * A_STR + ((idx & 7) << 2)] =
                        hh;
                    *(uint2*)&Al[so][(idx >> 3) * A_STR + ((idx & 7) << 2)] =
                        ll;
                    cvt_split4(pb[it], hh, ll);
                    *(uint2*)&Bh[so][(idx >> 5) * B_STR + ((idx & 31) << 2)] =
                        hh;
                    *(uint2*)&Bl[so][(idx >> 5) * B_STR + ((idx & 31) << 2)] =
                        ll;
                }
            }
        }
        __syncthreads();  // single barrier per tile
    }

    // ---- epilogue: add bias, store fp32 --------------------------------
    const int g4 = lane >> 2;
    const int l2 = (lane & 3) << 1;
#pragma unroll
    for (int nt = 0; nt < 4; nt++) {
        const int col = n0 + wn * 32 + nt * 8 + l2;
        float2 bv = *(const float2*)&bias[col];
#pragma unroll
        for (int mt = 0; mt < 4; mt++) {
            const int r = row0 + wm * 64 + mt * 16 + g4;
            float2 o0, o1;
            o0.x = d[mt][nt][0] + bv.x;
            o0.y = d[mt][nt][1] + bv.y;
            o1.x = d[mt][nt][2] + bv.x;
            o1.y = d[mt][nt][3] + bv.y;
            *(float2*)&g_xw[(size_t)r * 512 + col] = o0;
            *(float2*)&g_xw[(size_t)(r + 8) * 512 + col] = o1;
        }
    }
}

// ===========================================================================
// zero the tag arena (each replay, so stale tags never match)
// ===========================================================================
__global__ void init_hx() {
    unsigned long long* p = &g_hx[0][0][0][0][0];
    int i = blockIdx.x * blockDim.x + threadIdx.x;
#pragma unroll
    for (int q = 0; q < 4; q++) p[i + q * 16384] = 0ULL;
}

// ===========================================================================
// Phase 2: EXACT R7 tagged-value scan (best known)
// ===========================================================================
__global__ __launch_bounds__(256, 1) void rnn_scan(const float* __restrict__ W,
                                                   float* __restrict__ out) {
    __shared__ __align__(16) float dupA[8][64][4];                 // 8 KB
    __shared__ __align__(16) float dupB[8][64][4];                 // 8 KB
    __shared__ __align__(16) unsigned long long red[2][8][4][66];  // 33 KB

    const int bid = blockIdx.x;
    const int g = bid >> 3;   // group 0..15
    const int r0 = g << 2;    // 4 batch rows
    const int s = bid & 7;    // col split 0..7
    const int c0 = s << 6;    // 64 feature cols
    const int tid = threadIdx.x;
    const int cp = tid & 31;  // col-pair lane
    const int ks = tid >> 5;  // warp id == producer CTA watched

    unsigned long long wpk[64];
#pragma unroll
    for (int j = 0; j < 64; j++) {
        float2 w2 = *(const float2*)&W[(size_t)(512 + (ks << 6) + j) * 512 +
                                       c0 + (cp << 1)];
        PACK2(wpk[j], w2.x, w2.y);
    }

    const int rr = tid >> 6;  // epilogue row 0..3
    const int cc = tid & 63;  // epilogue col 0..63

    unsigned long long* const src0 = &g_hx[0][g][ks][cp][0];
    unsigned long long* const src1 = &g_hx[0][g][ks][cp + 32][0];
    const size_t bufstride = 16 * 8 * 64 * 4;

    unsigned long long* const dst = &g_hx[0][g][s][cc][rr];

    for (int t = 0; t < 1024; t++) {
        const int pb = t & 1;
        float xwv =
            g_xw[((size_t)(r0 + rr) * 1024 + (size_t)t) * 512 + c0 + cc];

        unsigned long long a0 = 0ULL, a1 = 0ULL, a2 = 0ULL, a3 = 0ULL;
        if (t > 0) {
            const unsigned long long* p0 = src0 + (size_t)pb * bufstride;
            const unsigned long long* p1 = src1 + (size_t)pb * bufstride;
            const unsigned int tg = (unsigned int)t;
            unsigned long long sv[8];
#pragma unroll
            for (int i = 0; i < 4; i++) {
                asm volatile("ld.relaxed.gpu.global.b64 %0, [%1];"
                             : "=l"(sv[i]) : "l"(p0 + i) : "memory");
                asm volatile("ld.relaxed.gpu.global.b64 %0, [%1];"
                             : "=l"(sv[4 + i]) : "l"(p1 + i) : "memory");
            }
            bool ok;
            do {
                ok = true;
#pragma unroll
                for (int i = 0; i < 4; i++) {
                    if ((unsigned int)(sv[i] >> 32) != tg) {
                        asm volatile("ld.relaxed.gpu.global.b64 %0, [%1];"
                                     : "=l"(sv[i]) : "l"(p0 + i) : "memory");
                        ok = false;
                    }
                    if ((unsigned int)(sv[4 + i] >> 32) != tg) {
                        asm volatile("ld.relaxed.gpu.global.b64 %0, [%1];"
                                     : "=l"(sv[4 + i]) : "l"(p1 + i)
                                     : "memory");
                        ok = false;
                    }
                }
            } while (!ok);

            float h0 = __uint_as_float((unsigned int)sv[0]);
            float h1 = __uint_as_float((unsigned int)sv[1]);
            float h2 = __uint_as_float((unsigned int)sv[2]);
            float h3 = __uint_as_float((unsigned int)sv[3]);
            *(float4*)&dupA[ks][cp][0] = make_float4(h0, h0, h1, h1);
            *(float4*)&dupB[ks][cp][0] = make_float4(h2, h2, h3, h3);
            h0 = __uint_as_float((unsigned int)sv[4]);
            h1 = __uint_as_float((unsigned int)sv[5]);
            h2 = __uint_as_float((unsigned int)sv[6]);
            h3 = __uint_as_float((unsigned int)sv[7]);
            *(float4*)&dupA[ks][cp + 32][0] = make_float4(h0, h0, h1, h1);
            *(float4*)&dupB[ks][cp + 32][0] =
                make_float4(h2, h2, h3, h3);
            __syncwarp();

            float* const hdA = &dupA[ks][0][0];
            float* const hdB = &dupB[ks][0][0];
#pragma unroll
            for (int j = 0; j < 64; j++) {
                ulonglong2 h01 = *(const ulonglong2*)(hdA + (j << 2));
                ulonglong2 h23 = *(const ulonglong2*)(hdB + (j << 2));
                FMA2(a0, h01.x, wpk[j], a0);
                FMA2(a1, h01.y, wpk[j], a1);
                FMA2(a2, h23.x, wpk[j], a2);
                FMA2(a3, h23.y, wpk[j], a3);
            }
        }
        red[pb][ks][0][cp] = a0;
        red[pb][ks][1][cp] = a1;
        red[pb][ks][2][cp] = a2;
        red[pb][ks][3][cp] = a3;
        __syncthreads();

        unsigned long long q0, q1, q2, q3;
        ADDF2(q0, red[pb][0][rr][cc >> 1], red[pb][1][rr][cc >> 1]);
        ADDF2(q1, red[pb][2][rr][cc >> 1], red[pb][3][rr][cc >> 1]);
        ADDF2(q2, red[pb][4][rr][cc >> 1], red[pb][5][rr][cc >> 1]);
        ADDF2(q3, red[pb][6][rr][cc >> 1], red[pb][7][rr][cc >> 1]);
        ADDF2(q0, q0, q1);
        ADDF2(q2, q2, q3);
        ADDF2(q0, q0, q2);
        float slo, shi;
        UNPACK2(slo, shi, q0);
        float v = tanhf(xwv + ((cc & 1) ? shi : slo));

        if (t < 1023) {
            unsigned long long pkt =
                ((unsigned long long)(unsigned int)(t + 1) << 32) |
                (unsigned long long)__float_as_uint(v);
            unsigned long long* d2 = dst + (size_t)((t + 1) & 1) * bufstride;
            asm volatile("st.relaxed.gpu.global.b64 [%0], %1;" ::"l"(d2),
                         "l"(pkt)
                         : "memory");
        }
        out[((size_t)(r0 + rr) * 1024 + (size_t)t) * 512 + c0 + cc] = v;
    }
}

// ---------------------------------------------------------------------------
extern "C" void kernel_launch(void* const* d_in, const int* in_sizes, int n_in,
                              void* d_out, int out_size) {
    const float* x = (const float*)d_in[0];  // (64, 1024, 512) f32
    const float* W = (const float*)d_in[1];  // (1024, 512) f32
    const float* b = (const float*)d_in[2];  // (512,) f32
    float* out = (float*)d_out;              // (64, 1024, 512) f32

    xw_mma<<<2048, 256>>>(x, W, b);
    init_hx<<<64, 256>>>();
    rnn_scan<<<128, 256>>>(W, out);
}